// round 5
// baseline (speedup 1.0000x reference)
#include <cuda_runtime.h>

#define EPSF 1e-10f

static const int R  = 32;
static const int NB = 256;          // co-resident blocks (<= 2/SM * 148)
static const int ROWS_PER_BLK = 64; // 2 tiles of 32

__device__ float2   g_scratch[NB * R * R];  // 2 MB partial Grams
__device__ float2   g_G[R * R];             // final Gram
__device__ float2   g_W[R * R];             // L^{-H}
__device__ unsigned g_bar[4];               // barrier counters (never reset)

typedef unsigned long long u64;

// ---- packed f32x2 helpers (FFMA2 only reachable via PTX) ----
__device__ __forceinline__ u64 pk2(float lo, float hi) {
    u64 r; asm("mov.b64 %0, {%1,%2};" : "=l"(r) : "f"(lo), "f"(hi)); return r;
}
__device__ __forceinline__ float2 upk2(u64 v) {
    float lo, hi; asm("mov.b64 {%0,%1}, %2;" : "=f"(lo), "=f"(hi) : "l"(v));
    return make_float2(lo, hi);
}
__device__ __forceinline__ u64 ffma2(u64 a, u64 b, u64 c) {
    u64 d; asm("fma.rn.f32x2 %0, %1, %2, %3;" : "=l"(d) : "l"(a), "l"(b), "l"(c)); return d;
}
__device__ __forceinline__ u64 fadd2(u64 a, u64 b) {
    u64 d; asm("add.rn.f32x2 %0, %1, %2;" : "=l"(d) : "l"(a), "l"(b)); return d;
}

// ---- software grid barrier (co-resident grid; wraparound-safe counters) ----
__device__ __forceinline__ void grid_barrier(int slot) {
    __syncthreads();
    if (threadIdx.x == 0) {
        __threadfence();                                   // release
        unsigned my = atomicAdd(&g_bar[slot], 1u);
        unsigned target = (my / (unsigned)NB + 1u) * (unsigned)NB;
        while ((int)(*((volatile unsigned*)&g_bar[slot]) - target) < 0) { }
        __threadfence();                                   // acquire
    }
    __syncthreads();
}

// ---------------------------------------------------------------------------
// Fused persistent kernel: gram -> reduce -> cholesky+inv -> apply
// ---------------------------------------------------------------------------
__global__ void __launch_bounds__(256, 2)
fused_kernel(const float2* __restrict__ x, float2* __restrict__ out) {
    __shared__ __align__(16) char sraw[32 * 1024 + 256];
    float4 (*a_dup)[R] = reinterpret_cast<float4(*)[R]>(sraw);          // 16KB
    float4 (*b_ns)[R]  = reinterpret_cast<float4(*)[R]>(sraw + 16384);  // 16KB
    u64*    red        = reinterpret_cast<u64*>(sraw);                  // reused
    float2* As         = reinterpret_cast<float2*>(sraw);               // reused (8.4KB)

    const int tid  = threadIdx.x;
    const int b    = blockIdx.x;
    const int lane = tid & 31;
    const int wid  = tid >> 5;

    // ======================= Phase 1: partial Gram =======================
    {
        const int mg  = tid >> 6;          // m-group 0..3
        const int t64 = tid & 63;
        const int i0  = (t64 >> 3) * 4;
        const int j0  = (t64 & 7) * 4;
        const int sr  = tid >> 3;          // staging row 0..31
        const int sc  = (tid & 7) * 4;     // staging col base (complex)

        const float2* xb = x + (size_t)b * (ROWS_PER_BLK * R);

        u64 acc[4][4];
        #pragma unroll
        for (int a_ = 0; a_ < 4; ++a_)
            #pragma unroll
            for (int c_ = 0; c_ < 4; ++c_) acc[a_][c_] = 0ull;

        for (int t = 0; t < 2; ++t) {
            float4 p0 = *(const float4*)(xb + (t * 32 + sr) * R + sc);
            float4 p1 = *(const float4*)(xb + (t * 32 + sr) * R + sc + 2);

            a_dup[sr][sc + 0] = make_float4(p0.x, p0.x, p0.y, p0.y);
            b_ns [sr][sc + 0] = make_float4(p0.x, p0.y, p0.y, -p0.x);
            a_dup[sr][sc + 1] = make_float4(p0.z, p0.z, p0.w, p0.w);
            b_ns [sr][sc + 1] = make_float4(p0.z, p0.w, p0.w, -p0.z);
            a_dup[sr][sc + 2] = make_float4(p1.x, p1.x, p1.y, p1.y);
            b_ns [sr][sc + 2] = make_float4(p1.x, p1.y, p1.y, -p1.x);
            a_dup[sr][sc + 3] = make_float4(p1.z, p1.z, p1.w, p1.w);
            b_ns [sr][sc + 3] = make_float4(p1.z, p1.w, p1.w, -p1.z);
            __syncthreads();

            #pragma unroll
            for (int mm = 0; mm < 8; ++mm) {
                const int m = mg + mm * 4;
                u64 A[4][2], B[4][2];
                #pragma unroll
                for (int d = 0; d < 4; ++d) {
                    float4 av = a_dup[m][i0 + d];
                    A[d][0] = pk2(av.x, av.y); A[d][1] = pk2(av.z, av.w);
                    float4 bv = b_ns[m][j0 + d];
                    B[d][0] = pk2(bv.x, bv.y); B[d][1] = pk2(bv.z, bv.w);
                }
                #pragma unroll
                for (int di = 0; di < 4; ++di)
                    #pragma unroll
                    for (int dj = 0; dj < 4; ++dj) {
                        acc[di][dj] = ffma2(A[di][0], B[dj][0], acc[di][dj]);
                        acc[di][dj] = ffma2(A[di][1], B[dj][1], acc[di][dj]);
                    }
            }
            __syncthreads();
        }

        // cross-m-group reduce in smem, group 0 writes the block's tile
        if (mg > 0) {
            u64* dst = red + ((mg - 1) * 64 + t64) * 16;
            #pragma unroll
            for (int di = 0; di < 4; ++di)
                #pragma unroll
                for (int dj = 0; dj < 4; ++dj) dst[di * 4 + dj] = acc[di][dj];
        }
        __syncthreads();
        if (mg == 0) {
            #pragma unroll
            for (int g = 0; g < 3; ++g) {
                const u64* srcp = red + (g * 64 + t64) * 16;
                #pragma unroll
                for (int di = 0; di < 4; ++di)
                    #pragma unroll
                    for (int dj = 0; dj < 4; ++dj)
                        acc[di][dj] = fadd2(acc[di][dj], srcp[di * 4 + dj]);
            }
            float4* gout = reinterpret_cast<float4*>(g_scratch + b * (R * R));
            #pragma unroll
            for (int di = 0; di < 4; ++di) {
                float2 c0 = upk2(acc[di][0]), c1 = upk2(acc[di][1]);
                float2 c2 = upk2(acc[di][2]), c3 = upk2(acc[di][3]);
                int base = ((i0 + di) * R + j0) >> 1;
                gout[base]     = make_float4(c0.x, c0.y, c1.x, c1.y);
                gout[base + 1] = make_float4(c2.x, c2.y, c3.x, c3.y);
            }
        }
    }

    grid_barrier(0);

    // =============== Phase 2: fold 256 tiles -> final G ==================
    if (b < 8) {
        const float* srcf = (const float*)g_scratch;
        const int e = b * 256 + tid;            // float index 0..2047
        float s = 0.f;
        #pragma unroll 8
        for (int i = 0; i < NB; ++i)
            s += __ldcg(srcf + (size_t)i * 2048 + e);
        ((float*)g_G)[e] = s;
    }

    grid_barrier(1);

    // ====== Phase 3: block 0 — Cholesky (in smem) + backsub -> W ========
    if (b == 0) {
        for (int e = tid; e < R * R; e += 256)
            As[(e >> 5) * 33 + (e & 31)] = __ldcg(&g_G[e]);
        __syncthreads();

        for (int k = 0; k < R; ++k) {
            float akk = As[k * 33 + k].x;
            float rd  = rsqrtf(akk + EPSF);
            __syncthreads();                       // reads before writes
            if (tid == 0) As[k * 33 + k] = make_float2((akk + EPSF) * rd, 0.f);
            if (tid > k && tid < 32) {
                float2 l = As[tid * 33 + k];
                l.x *= rd; l.y *= rd;
                As[tid * 33 + k] = l;
            }
            __syncthreads();
            // trailing update (lower triangle only): A[p][q] -= L[p][k]*conj(L[q][k])
            #pragma unroll
            for (int s = 0; s < 4; ++s) {
                int p = (tid >> 5) + 8 * s;
                int q = tid & 31;
                if (p > k && q > k && q <= p) {
                    float2 lp = As[p * 33 + k], lq = As[q * 33 + k];
                    float2 a = As[p * 33 + q];
                    a.x -= lp.x * lq.x + lp.y * lq.y;
                    a.y -= lp.y * lq.x - lp.x * lq.y;
                    As[p * 33 + q] = a;
                }
            }
            __syncthreads();
        }

        // backsub: warp w solves columns j = w, w+8, w+16, w+24 of L^H W = I
        {
            const float invd = 1.0f / As[lane * 33 + lane].x;
            #pragma unroll
            for (int jj = 0; jj < 4; ++jj) {
                int j = wid + jj * 8;
                float2 accw = make_float2(0.f, 0.f);
                float2 wp   = make_float2(0.f, 0.f);
                for (int qq = j; qq >= 0; --qq) {
                    float cre = (((lane == j) ? 1.f : 0.f) - accw.x) * invd;
                    float cim = (-accw.y) * invd;
                    float wr = __shfl_sync(0xffffffffu, cre, qq);
                    float wi = __shfl_sync(0xffffffffu, cim, qq);
                    if (lane == qq) { wp.x = wr; wp.y = wi; }
                    float2 lqp = As[qq * 33 + lane];   // L[qq][lane]
                    if (lane < qq) {
                        accw.x += lqp.x * wr + lqp.y * wi;  // conj(L[qq][p]) * w_qq
                        accw.y += lqp.x * wi - lqp.y * wr;
                    }
                }
                g_W[lane * R + j] = wp;   // W[k][j]
            }
        }
    }

    grid_barrier(2);

    // ================= Phase 4: apply  Q = X * W =========================
    {
        float wr[R], wi[R];
        #pragma unroll
        for (int k = 0; k < R; ++k) {
            float2 wv = __ldcg(&g_W[k * R + lane]);
            wr[k] = wv.x; wi[k] = wv.y;
        }

        const int gw = b * 8 + wid;
        const int m0 = gw * 8;
        #pragma unroll
        for (int r = 0; r < 8; ++r) {
            int m = m0 + r;
            float2 v = x[m * R + lane];
            float or_ = 0.f, oi_ = 0.f;
            #pragma unroll
            for (int k = 0; k < R; ++k) {
                float ar = __shfl_sync(0xffffffffu, v.x, k);
                float ai = __shfl_sync(0xffffffffu, v.y, k);
                or_ += ar * wr[k] - ai * wi[k];
                oi_ += ar * wi[k] + ai * wr[k];
            }
            out[m * R + lane] = make_float2(or_, oi_);
        }
    }
}

// ---------------------------------------------------------------------------
extern "C" void kernel_launch(void* const* d_in, const int* in_sizes, int n_in,
                              void* d_out, int out_size) {
    const float2* x  = (const float2*)d_in[0];
    float2* out      = (float2*)d_out;

    fused_kernel<<<NB, 256>>>(x, out);
}

// round 6
// speedup vs baseline: 1.2275x; 1.2275x over previous
#include <cuda_runtime.h>

#define EPSF 1e-10f

static const int R  = 32;
static const int NB = 256;          // co-resident blocks (<= 2/SM * 148)
static const int ROWS_PER_BLK = 64; // 2 tiles of 32

__device__ float2   g_scratch[NB * R * R];  // 2 MB partial Grams
__device__ float2   g_red[32 * R * R];      // 256 KB stage-1 folded tiles
__device__ float2   g_L[R * R];             // Cholesky factor
__device__ float2   g_W[R * R];             // L^{-H}
__device__ unsigned g_bar[4];               // barrier counters (never reset)

typedef unsigned long long u64;

// ---- packed f32x2 helpers (FFMA2 only reachable via PTX) ----
__device__ __forceinline__ u64 pk2(float lo, float hi) {
    u64 r; asm("mov.b64 %0, {%1,%2};" : "=l"(r) : "f"(lo), "f"(hi)); return r;
}
__device__ __forceinline__ float2 upk2(u64 v) {
    float lo, hi; asm("mov.b64 {%0,%1}, %2;" : "=f"(lo), "=f"(hi) : "l"(v));
    return make_float2(lo, hi);
}
__device__ __forceinline__ u64 ffma2(u64 a, u64 b, u64 c) {
    u64 d; asm("fma.rn.f32x2 %0, %1, %2, %3;" : "=l"(d) : "l"(a), "l"(b), "l"(c)); return d;
}
__device__ __forceinline__ u64 fadd2(u64 a, u64 b) {
    u64 d; asm("add.rn.f32x2 %0, %1, %2;" : "=l"(d) : "l"(a), "l"(b)); return d;
}

// ---- software grid barrier (co-resident grid; wraparound-safe counters) ----
__device__ __forceinline__ void grid_barrier(int slot) {
    __syncthreads();
    if (threadIdx.x == 0) {
        __threadfence();                                   // release
        unsigned my = atomicAdd(&g_bar[slot], 1u);
        unsigned target = (my / (unsigned)NB + 1u) * (unsigned)NB;
        while ((int)(*((volatile unsigned*)&g_bar[slot]) - target) < 0) { }
        __threadfence();                                   // acquire
    }
    __syncthreads();
}

// ---------------------------------------------------------------------------
// Fused persistent kernel: gram -> fold -> cholesky -> backsub -> apply
// ---------------------------------------------------------------------------
__global__ void __launch_bounds__(256, 2)
fused_kernel(const float2* __restrict__ x, float2* __restrict__ out) {
    __shared__ __align__(16) char sraw[32 * 1024 + 512];
    float4 (*a_dup)[R] = reinterpret_cast<float4(*)[R]>(sraw);          // 16KB
    float4 (*b_ns)[R]  = reinterpret_cast<float4(*)[R]>(sraw + 16384);  // 16KB
    u64*    red        = reinterpret_cast<u64*>(sraw);                  // reused
    float2* As         = reinterpret_cast<float2*>(sraw);               // reused
    float2* colbuf     = reinterpret_cast<float2*>(sraw + 28 * 1024);   // [2][32]

    const int tid  = threadIdx.x;
    const int b    = blockIdx.x;
    const int lane = tid & 31;
    const int wid  = tid >> 5;

    // ======================= Phase 1: partial Gram =======================
    {
        const int mg  = tid >> 6;          // m-group 0..3
        const int t64 = tid & 63;
        const int i0  = (t64 >> 3) * 4;
        const int j0  = (t64 & 7) * 4;
        const int sr  = tid >> 3;          // staging row 0..31
        const int sc  = (tid & 7) * 4;     // staging col base (complex)

        const float2* xb = x + (size_t)b * (ROWS_PER_BLK * R);

        u64 acc[4][4];
        #pragma unroll
        for (int a_ = 0; a_ < 4; ++a_)
            #pragma unroll
            for (int c_ = 0; c_ < 4; ++c_) acc[a_][c_] = 0ull;

        for (int t = 0; t < 2; ++t) {
            float4 p0 = *(const float4*)(xb + (t * 32 + sr) * R + sc);
            float4 p1 = *(const float4*)(xb + (t * 32 + sr) * R + sc + 2);

            a_dup[sr][sc + 0] = make_float4(p0.x, p0.x, p0.y, p0.y);
            b_ns [sr][sc + 0] = make_float4(p0.x, p0.y, p0.y, -p0.x);
            a_dup[sr][sc + 1] = make_float4(p0.z, p0.z, p0.w, p0.w);
            b_ns [sr][sc + 1] = make_float4(p0.z, p0.w, p0.w, -p0.z);
            a_dup[sr][sc + 2] = make_float4(p1.x, p1.x, p1.y, p1.y);
            b_ns [sr][sc + 2] = make_float4(p1.x, p1.y, p1.y, -p1.x);
            a_dup[sr][sc + 3] = make_float4(p1.z, p1.z, p1.w, p1.w);
            b_ns [sr][sc + 3] = make_float4(p1.z, p1.w, p1.w, -p1.z);
            __syncthreads();

            #pragma unroll
            for (int mm = 0; mm < 8; ++mm) {
                const int m = mg + mm * 4;
                u64 A[4][2], B[4][2];
                #pragma unroll
                for (int d = 0; d < 4; ++d) {
                    float4 av = a_dup[m][i0 + d];
                    A[d][0] = pk2(av.x, av.y); A[d][1] = pk2(av.z, av.w);
                    float4 bv = b_ns[m][j0 + d];
                    B[d][0] = pk2(bv.x, bv.y); B[d][1] = pk2(bv.z, bv.w);
                }
                #pragma unroll
                for (int di = 0; di < 4; ++di)
                    #pragma unroll
                    for (int dj = 0; dj < 4; ++dj) {
                        acc[di][dj] = ffma2(A[di][0], B[dj][0], acc[di][dj]);
                        acc[di][dj] = ffma2(A[di][1], B[dj][1], acc[di][dj]);
                    }
            }
            __syncthreads();
        }

        // cross-m-group reduce in smem, group 0 writes the block's tile
        if (mg > 0) {
            u64* dst = red + ((mg - 1) * 64 + t64) * 16;
            #pragma unroll
            for (int di = 0; di < 4; ++di)
                #pragma unroll
                for (int dj = 0; dj < 4; ++dj) dst[di * 4 + dj] = acc[di][dj];
        }
        __syncthreads();
        if (mg == 0) {
            #pragma unroll
            for (int g = 0; g < 3; ++g) {
                const u64* srcp = red + (g * 64 + t64) * 16;
                #pragma unroll
                for (int di = 0; di < 4; ++di)
                    #pragma unroll
                    for (int dj = 0; dj < 4; ++dj)
                        acc[di][dj] = fadd2(acc[di][dj], srcp[di * 4 + dj]);
            }
            float4* gout = reinterpret_cast<float4*>(g_scratch + b * (R * R));
            #pragma unroll
            for (int di = 0; di < 4; ++di) {
                float2 c0 = upk2(acc[di][0]), c1 = upk2(acc[di][1]);
                float2 c2 = upk2(acc[di][2]), c3 = upk2(acc[di][3]);
                int base = ((i0 + di) * R + j0) >> 1;
                gout[base]     = make_float4(c0.x, c0.y, c1.x, c1.y);
                gout[base + 1] = make_float4(c2.x, c2.y, c3.x, c3.y);
            }
        }
    }

    grid_barrier(0);

    // ============ Phase 2a: 32 blocks fold 8 tiles each (coalesced) ======
    if (b < 32) {
        const float4* src = (const float4*)g_scratch + (size_t)b * 8 * 512;
        float4* dst = (float4*)g_red + (size_t)b * 512;
        #pragma unroll
        for (int h = 0; h < 2; ++h) {
            int e = tid + h * 256;
            float4 s = __ldcg(src + e);
            #pragma unroll
            for (int i = 1; i < 8; ++i) {
                float4 a = __ldcg(src + (size_t)i * 512 + e);
                s.x += a.x; s.y += a.y; s.z += a.z; s.w += a.w;
            }
            dst[e] = s;
        }
    }

    grid_barrier(1);

    // ====== Phase 2b+3: block 0 — fold 32 -> G, register Cholesky -> L ===
    if (b == 0) {
        // fold 32 tiles into smem As (padded stride 33 complex)
        const float4* src = (const float4*)g_red;
        #pragma unroll
        for (int h = 0; h < 2; ++h) {
            int f4 = tid + h * 256;
            float4 s = __ldcg(src + f4);
            #pragma unroll
            for (int i = 1; i < 32; ++i) {
                float4 a = __ldcg(src + (size_t)i * 512 + f4);
                s.x += a.x; s.y += a.y; s.z += a.z; s.w += a.w;
            }
            int c = f4 * 2;
            As[(c >> 5) * 33 + (c & 31)]             = make_float2(s.x, s.y);
            As[((c + 1) >> 5) * 33 + ((c + 1) & 31)] = make_float2(s.z, s.w);
        }
        __syncthreads();

        // register (p,q)-parallel Cholesky: thread holds A[w+8s][lane], s=0..3
        float2 a4[4];
        #pragma unroll
        for (int s = 0; s < 4; ++s) a4[s] = As[(wid + 8 * s) * 33 + lane];

        for (int k = 0; k < R; ++k) {
            float2* cb = colbuf + (k & 1) * 32;
            if (lane == k) {
                #pragma unroll
                for (int s = 0; s < 4; ++s) cb[wid + 8 * s] = a4[s];
            }
            __syncthreads();
            float dkk = cb[k].x;
            float rd  = rsqrtf(dkk + EPSF);
            float2 cq = cb[lane];
            float2 lq = make_float2(cq.x * rd, cq.y * rd);
            #pragma unroll
            for (int s = 0; s < 4; ++s) {
                int p = wid + 8 * s;
                float2 cp = cb[p];
                float2 lp = make_float2(cp.x * rd, cp.y * rd);
                if (p > k && lane > k) {
                    a4[s].x -= lp.x * lq.x + lp.y * lq.y;   // -= L[p][k]*conj(L[q][k])
                    a4[s].y -= lp.y * lq.x - lp.x * lq.y;
                }
                if (lane == k) {
                    if (p == k)      a4[s] = make_float2((dkk + EPSF) * rd, 0.f);
                    else if (p > k)  a4[s] = lp;
                }
            }
        }
        // publish L (lower triangle + diag valid; upper is don't-care)
        #pragma unroll
        for (int s = 0; s < 4; ++s) g_L[(wid + 8 * s) * R + lane] = a4[s];
    }

    grid_barrier(2);

    // ========= Phase 3b: blocks 0-3 backsub, one warp per column =========
    if (b < 4) {
        for (int e = tid; e < R * R; e += 256)
            As[(e >> 5) * 33 + (e & 31)] = __ldcg(&g_L[e]);
        __syncthreads();

        const int j = b * 8 + wid;
        const float invd = 1.0f / As[lane * 33 + lane].x;
        float2 accw = make_float2(0.f, 0.f);
        float2 wp   = make_float2(0.f, 0.f);
        for (int qq = j; qq >= 0; --qq) {
            float cre = (((lane == j) ? 1.f : 0.f) - accw.x) * invd;
            float cim = (-accw.y) * invd;
            float wr = __shfl_sync(0xffffffffu, cre, qq);
            float wi = __shfl_sync(0xffffffffu, cim, qq);
            if (lane == qq) { wp.x = wr; wp.y = wi; }
            float2 lqp = As[qq * 33 + lane];        // L[qq][lane]
            if (lane < qq) {
                accw.x += lqp.x * wr + lqp.y * wi;  // conj(L[qq][p]) * w_qq
                accw.y += lqp.x * wi - lqp.y * wr;
            }
        }
        g_W[lane * R + j] = wp;   // W[k][j]
    }

    grid_barrier(3);

    // ================= Phase 4: apply  Q = X * W =========================
    {
        float wr[R], wi[R];
        #pragma unroll
        for (int k = 0; k < R; ++k) {
            float2 wv = __ldcg(&g_W[k * R + lane]);
            wr[k] = wv.x; wi[k] = wv.y;
        }

        const int gw = b * 8 + wid;
        const int m0 = gw * 8;
        #pragma unroll
        for (int r = 0; r < 8; ++r) {
            int m = m0 + r;
            float2 v = x[m * R + lane];
            float or_ = 0.f, oi_ = 0.f;
            #pragma unroll
            for (int k = 0; k < R; ++k) {
                float ar = __shfl_sync(0xffffffffu, v.x, k);
                float ai = __shfl_sync(0xffffffffu, v.y, k);
                or_ += ar * wr[k] - ai * wi[k];
                oi_ += ar * wi[k] + ai * wr[k];
            }
            out[m * R + lane] = make_float2(or_, oi_);
        }
    }
}

// ---------------------------------------------------------------------------
extern "C" void kernel_launch(void* const* d_in, const int* in_sizes, int n_in,
                              void* d_out, int out_size) {
    const float2* x  = (const float2*)d_in[0];
    float2* out      = (float2*)d_out;

    fused_kernel<<<NB, 256>>>(x, out);
}

// round 7
// speedup vs baseline: 1.2515x; 1.0195x over previous
#include <cuda_runtime.h>

#define EPSF 1e-10f

static const int R  = 32;
static const int NB = 256;          // co-resident blocks (<= 2/SM * 148)
static const int ROWS_PER_BLK = 64; // 2 tiles of 32

__device__ float2   g_scratch[NB * R * R];  // 2 MB partial Grams
__device__ float2   g_red[32 * R * R];      // 256 KB level-1 folds
__device__ float2   g_red2[4 * R * R];      // 32 KB level-2 folds
__device__ float2   g_L[R * R];             // Cholesky factor
__device__ float2   g_W[R * R];             // L^{-H}
// sync counters (never reset): [0..31] gram groups (8 arr each),
// [32..35] fold1 groups (8 arr each), [36] fold2 (4 arr),
// [37] chol (1 arr), [38] W ready (4 arr)
__device__ unsigned g_sync[48];

typedef unsigned long long u64;

// ---- packed f32x2 helpers (FFMA2 only reachable via PTX) ----
__device__ __forceinline__ u64 pk2(float lo, float hi) {
    u64 r; asm("mov.b64 %0, {%1,%2};" : "=l"(r) : "f"(lo), "f"(hi)); return r;
}
__device__ __forceinline__ float2 upk2(u64 v) {
    float lo, hi; asm("mov.b64 {%0,%1}, %2;" : "=f"(lo), "=f"(hi) : "l"(v));
    return make_float2(lo, hi);
}
__device__ __forceinline__ u64 ffma2(u64 a, u64 b, u64 c) {
    u64 d; asm("fma.rn.f32x2 %0, %1, %2, %3;" : "=l"(d) : "l"(a), "l"(b), "l"(c)); return d;
}
__device__ __forceinline__ u64 fadd2(u64 a, u64 b) {
    u64 d; asm("add.rn.f32x2 %0, %1, %2;" : "=l"(d) : "l"(a), "l"(b)); return d;
}

// ---- flag primitives (tid-0 only; caller wraps with __syncthreads) ----
__device__ __forceinline__ unsigned arrive(unsigned* ctr) {
    __threadfence();                       // release all prior writes
    return atomicAdd(ctr, 1u);
}
__device__ __forceinline__ void spin_ge(unsigned* ctr, unsigned target) {
    while ((int)(*((volatile unsigned*)ctr) - target) < 0) { }
    __threadfence();                       // acquire
}

// ---------------------------------------------------------------------------
// Fused persistent kernel, producer-consumer synchronized:
//   gram(256) -> fold1(32) -> fold2(4) -> chol(1) -> backsub(4) -> apply(256)
// ---------------------------------------------------------------------------
__global__ void __launch_bounds__(256, 2)
fused_kernel(const float2* __restrict__ x, float2* __restrict__ out) {
    __shared__ __align__(16) char sraw[32 * 1024 + 512];
    float4 (*a_dup)[R] = reinterpret_cast<float4(*)[R]>(sraw);          // 16KB
    float4 (*b_ns)[R]  = reinterpret_cast<float4(*)[R]>(sraw + 16384);  // 16KB
    u64*    red        = reinterpret_cast<u64*>(sraw);                  // reused
    float2* As         = reinterpret_cast<float2*>(sraw);               // reused
    float2* colbuf     = reinterpret_cast<float2*>(sraw + 28 * 1024);   // [2][32]

    const int tid  = threadIdx.x;
    const int b    = blockIdx.x;
    const int lane = tid & 31;
    const int wid  = tid >> 5;

    // ======================= Phase 1: partial Gram =======================
    {
        const int mg  = tid >> 6;
        const int t64 = tid & 63;
        const int i0  = (t64 >> 3) * 4;
        const int j0  = (t64 & 7) * 4;
        const int sr  = tid >> 3;
        const int sc  = (tid & 7) * 4;

        const float2* xb = x + (size_t)b * (ROWS_PER_BLK * R);

        u64 acc[4][4];
        #pragma unroll
        for (int a_ = 0; a_ < 4; ++a_)
            #pragma unroll
            for (int c_ = 0; c_ < 4; ++c_) acc[a_][c_] = 0ull;

        for (int t = 0; t < 2; ++t) {
            float4 p0 = *(const float4*)(xb + (t * 32 + sr) * R + sc);
            float4 p1 = *(const float4*)(xb + (t * 32 + sr) * R + sc + 2);

            a_dup[sr][sc + 0] = make_float4(p0.x, p0.x, p0.y, p0.y);
            b_ns [sr][sc + 0] = make_float4(p0.x, p0.y, p0.y, -p0.x);
            a_dup[sr][sc + 1] = make_float4(p0.z, p0.z, p0.w, p0.w);
            b_ns [sr][sc + 1] = make_float4(p0.z, p0.w, p0.w, -p0.z);
            a_dup[sr][sc + 2] = make_float4(p1.x, p1.x, p1.y, p1.y);
            b_ns [sr][sc + 2] = make_float4(p1.x, p1.y, p1.y, -p1.x);
            a_dup[sr][sc + 3] = make_float4(p1.z, p1.z, p1.w, p1.w);
            b_ns [sr][sc + 3] = make_float4(p1.z, p1.w, p1.w, -p1.z);
            __syncthreads();

            #pragma unroll
            for (int mm = 0; mm < 8; ++mm) {
                const int m = mg + mm * 4;
                u64 A[4][2], B[4][2];
                #pragma unroll
                for (int d = 0; d < 4; ++d) {
                    float4 av = a_dup[m][i0 + d];
                    A[d][0] = pk2(av.x, av.y); A[d][1] = pk2(av.z, av.w);
                    float4 bv = b_ns[m][j0 + d];
                    B[d][0] = pk2(bv.x, bv.y); B[d][1] = pk2(bv.z, bv.w);
                }
                #pragma unroll
                for (int di = 0; di < 4; ++di)
                    #pragma unroll
                    for (int dj = 0; dj < 4; ++dj) {
                        acc[di][dj] = ffma2(A[di][0], B[dj][0], acc[di][dj]);
                        acc[di][dj] = ffma2(A[di][1], B[dj][1], acc[di][dj]);
                    }
            }
            __syncthreads();
        }

        if (mg > 0) {
            u64* dst = red + ((mg - 1) * 64 + t64) * 16;
            #pragma unroll
            for (int di = 0; di < 4; ++di)
                #pragma unroll
                for (int dj = 0; dj < 4; ++dj) dst[di * 4 + dj] = acc[di][dj];
        }
        __syncthreads();
        if (mg == 0) {
            #pragma unroll
            for (int g = 0; g < 3; ++g) {
                const u64* srcp = red + (g * 64 + t64) * 16;
                #pragma unroll
                for (int di = 0; di < 4; ++di)
                    #pragma unroll
                    for (int dj = 0; dj < 4; ++dj)
                        acc[di][dj] = fadd2(acc[di][dj], srcp[di * 4 + dj]);
            }
            float4* gout = reinterpret_cast<float4*>(g_scratch + b * (R * R));
            #pragma unroll
            for (int di = 0; di < 4; ++di) {
                float2 c0 = upk2(acc[di][0]), c1 = upk2(acc[di][1]);
                float2 c2 = upk2(acc[di][2]), c3 = upk2(acc[di][3]);
                int base = ((i0 + di) * R + j0) >> 1;
                gout[base]     = make_float4(c0.x, c0.y, c1.x, c1.y);
                gout[base + 1] = make_float4(c2.x, c2.y, c3.x, c3.y);
            }
        }
    }
    __syncthreads();

    // epoch ticket from own gram-group arrival (8 arrivals/group/replay)
    unsigned e = 0;
    if (tid == 0) e = arrive(&g_sync[b >> 3]) >> 3;

    // ============ Phase 2a: blocks 0..31 fold 8 scratch tiles ============
    if (b < 32) {
        if (tid == 0) spin_ge(&g_sync[b], (e + 1) * 8);
        __syncthreads();
        const float4* src = (const float4*)g_scratch + (size_t)b * 8 * 512;
        float4* dst = (float4*)g_red + (size_t)b * 512;
        #pragma unroll
        for (int h = 0; h < 2; ++h) {
            int i4 = tid + h * 256;
            float4 s = __ldcg(src + i4);
            #pragma unroll
            for (int i = 1; i < 8; ++i) {
                float4 a = __ldcg(src + (size_t)i * 512 + i4);
                s.x += a.x; s.y += a.y; s.z += a.z; s.w += a.w;
            }
            dst[i4] = s;
        }
        __syncthreads();
        if (tid == 0) arrive(&g_sync[32 + (b >> 3)]);
    }

    // ============ Phase 2b: blocks 0..3 fold 8 red tiles =================
    if (b < 4) {
        if (tid == 0) spin_ge(&g_sync[32 + b], (e + 1) * 8);
        __syncthreads();
        const float4* src = (const float4*)g_red + (size_t)b * 8 * 512;
        float4* dst = (float4*)g_red2 + (size_t)b * 512;
        #pragma unroll
        for (int h = 0; h < 2; ++h) {
            int i4 = tid + h * 256;
            float4 s = __ldcg(src + i4);
            #pragma unroll
            for (int i = 1; i < 8; ++i) {
                float4 a = __ldcg(src + (size_t)i * 512 + i4);
                s.x += a.x; s.y += a.y; s.z += a.z; s.w += a.w;
            }
            dst[i4] = s;
        }
        __syncthreads();
        if (tid == 0) arrive(&g_sync[36]);
    }

    // ====== Phase 2c+3: block 0 — fold 4 -> G, register Cholesky -> L ====
    if (b == 0) {
        if (tid == 0) spin_ge(&g_sync[36], (e + 1) * 4);
        __syncthreads();
        const float4* src = (const float4*)g_red2;
        #pragma unroll
        for (int h = 0; h < 2; ++h) {
            int f4 = tid + h * 256;
            float4 s = __ldcg(src + f4);
            #pragma unroll
            for (int i = 1; i < 4; ++i) {
                float4 a = __ldcg(src + (size_t)i * 512 + f4);
                s.x += a.x; s.y += a.y; s.z += a.z; s.w += a.w;
            }
            int c = f4 * 2;
            As[(c >> 5) * 33 + (c & 31)]             = make_float2(s.x, s.y);
            As[((c + 1) >> 5) * 33 + ((c + 1) & 31)] = make_float2(s.z, s.w);
        }
        __syncthreads();

        // register (p,q)-parallel Cholesky: thread holds A[wid+8s][lane]
        float2 a4[4];
        #pragma unroll
        for (int s = 0; s < 4; ++s) a4[s] = As[(wid + 8 * s) * 33 + lane];

        for (int k = 0; k < R; ++k) {
            float2* cb = colbuf + (k & 1) * 32;
            if (lane == k) {
                #pragma unroll
                for (int s = 0; s < 4; ++s) cb[wid + 8 * s] = a4[s];
            }
            __syncthreads();
            float dkk = cb[k].x;
            float rd  = rsqrtf(dkk + EPSF);
            float2 cq = cb[lane];
            float2 lq = make_float2(cq.x * rd, cq.y * rd);
            #pragma unroll
            for (int s = 0; s < 4; ++s) {
                int p = wid + 8 * s;
                float2 cp = cb[p];
                float2 lp = make_float2(cp.x * rd, cp.y * rd);
                if (p > k && lane > k) {
                    a4[s].x -= lp.x * lq.x + lp.y * lq.y;
                    a4[s].y -= lp.y * lq.x - lp.x * lq.y;
                }
                if (lane == k) {
                    if (p == k)      a4[s] = make_float2((dkk + EPSF) * rd, 0.f);
                    else if (p > k)  a4[s] = lp;
                }
            }
        }
        #pragma unroll
        for (int s = 0; s < 4; ++s) g_L[(wid + 8 * s) * R + lane] = a4[s];
        __syncthreads();
        if (tid == 0) arrive(&g_sync[37]);
    }

    // ========= Phase 3b: blocks 0-3 backsub, one warp per column =========
    if (b < 4) {
        if (tid == 0) spin_ge(&g_sync[37], e + 1);
        __syncthreads();
        for (int el = tid; el < R * R; el += 256)
            As[(el >> 5) * 33 + (el & 31)] = __ldcg(&g_L[el]);
        __syncthreads();

        const int j = b * 8 + wid;
        const float invd = 1.0f / As[lane * 33 + lane].x;
        float2 accw = make_float2(0.f, 0.f);
        float2 wp   = make_float2(0.f, 0.f);
        for (int qq = j; qq >= 0; --qq) {
            float cre = (((lane == j) ? 1.f : 0.f) - accw.x) * invd;
            float cim = (-accw.y) * invd;
            float wr = __shfl_sync(0xffffffffu, cre, qq);
            float wi = __shfl_sync(0xffffffffu, cim, qq);
            if (lane == qq) { wp.x = wr; wp.y = wi; }
            float2 lqp = As[qq * 33 + lane];
            if (lane < qq) {
                accw.x += lqp.x * wr + lqp.y * wi;
                accw.y += lqp.x * wi - lqp.y * wr;
            }
        }
        g_W[lane * R + j] = wp;   // W[k][j]
        __syncthreads();
        if (tid == 0) arrive(&g_sync[38]);
    }

    // ================= Phase 4: apply  Q = X * W =========================
    if (tid == 0) spin_ge(&g_sync[38], (e + 1) * 4);
    __syncthreads();
    {
        float wr[R], wi[R];
        #pragma unroll
        for (int k = 0; k < R; ++k) {
            float2 wv = __ldcg(&g_W[k * R + lane]);
            wr[k] = wv.x; wi[k] = wv.y;
        }

        const int gw = b * 8 + wid;
        const int m0 = gw * 8;
        #pragma unroll
        for (int r = 0; r < 8; ++r) {
            int m = m0 + r;
            float2 v = x[m * R + lane];
            float or_ = 0.f, oi_ = 0.f;
            #pragma unroll
            for (int k = 0; k < R; ++k) {
                float ar = __shfl_sync(0xffffffffu, v.x, k);
                float ai = __shfl_sync(0xffffffffu, v.y, k);
                or_ += ar * wr[k] - ai * wi[k];
                oi_ += ar * wi[k] + ai * wr[k];
            }
            out[m * R + lane] = make_float2(or_, oi_);
        }
    }
}

// ---------------------------------------------------------------------------
extern "C" void kernel_launch(void* const* d_in, const int* in_sizes, int n_in,
                              void* d_out, int out_size) {
    const float2* x  = (const float2*)d_in[0];
    float2* out      = (float2*)d_out;

    fused_kernel<<<NB, 256>>>(x, out);
}